// round 3
// baseline (speedup 1.0000x reference)
#include <cuda_runtime.h>
#include <cuda_bf16.h>
#include <cstdint>

// AggregationLayer: y[s] = mean over edges e with segment_ids[e]==s of
//                   layer_values[gather_idx[e], :]
// d_in[0]: layer_values f32 [N_SRC*64]
// d_in[1]: gather_idx   i32 [E]
// d_in[2]: segment_ids  i32 [E] (sorted ascending)
// out: f32 [n_seg*64]

#define D 64

// CSR row offsets scratch (n_seg <= 1M supported). +1 for the terminator.
__device__ int g_begin[1048577];

__global__ void __launch_bounds__(256)
build_csr_kernel(const int* __restrict__ segs, int E, int n_seg)
{
    int e = blockIdx.x * blockDim.x + threadIdx.x;
    if (e >= E) return;
    int s  = __ldg(segs + e);
    int sp = (e == 0) ? -1 : __ldg(segs + e - 1);
    // this thread owns boundaries (sp, s]
    for (int t = sp + 1; t <= s; ++t) g_begin[t] = e;
    if (e == E - 1) {
        for (int t = s + 1; t <= n_seg; ++t) g_begin[t] = E;
    }
}

__global__ void __launch_bounds__(256)
agg_seg_mean_kernel(const float* __restrict__ vals,
                    const int*   __restrict__ gidx,
                    float*       __restrict__ out,
                    int n_seg)
{
    const int warp_id = (blockIdx.x * blockDim.x + threadIdx.x) >> 5;
    const int lane    = threadIdx.x & 31;
    if (warp_id >= n_seg) return;
    const int s = warp_id;

    const int begin = __ldg(&g_begin[s]);
    const int end   = __ldg(&g_begin[s + 1]);

    const float2* __restrict__ vals2 = reinterpret_cast<const float2*>(vals);

    float ax = 0.f, ay = 0.f;

    for (int base = begin; base < end; base += 32) {
        const int n = min(32, end - base);
        // one coalesced load grabs up to 32 edge indices for the whole warp
        int myidx = 0;
        if (lane < n) myidx = __ldg(gidx + base + lane);

        int j = 0;
        for (; j + 4 <= n; j += 4) {
            int r0 = __shfl_sync(0xffffffffu, myidx, j + 0);
            int r1 = __shfl_sync(0xffffffffu, myidx, j + 1);
            int r2 = __shfl_sync(0xffffffffu, myidx, j + 2);
            int r3 = __shfl_sync(0xffffffffu, myidx, j + 3);
            float2 v0 = __ldg(vals2 + (size_t)r0 * (D/2) + lane);
            float2 v1 = __ldg(vals2 + (size_t)r1 * (D/2) + lane);
            float2 v2 = __ldg(vals2 + (size_t)r2 * (D/2) + lane);
            float2 v3 = __ldg(vals2 + (size_t)r3 * (D/2) + lane);
            ax += v0.x + v1.x + v2.x + v3.x;
            ay += v0.y + v1.y + v2.y + v3.y;
        }
        for (; j < n; ++j) {
            int r = __shfl_sync(0xffffffffu, myidx, j);
            float2 v = __ldg(vals2 + (size_t)r * (D/2) + lane);
            ax += v.x;
            ay += v.y;
        }
    }

    const int cnt = end - begin;
    const float inv = 1.0f / (float)max(cnt, 1);
    float2 res;
    res.x = ax * inv;
    res.y = ay * inv;
    reinterpret_cast<float2*>(out)[(size_t)s * (D/2) + lane] = res;
}

extern "C" void kernel_launch(void* const* d_in, const int* in_sizes, int n_in,
                              void* d_out, int out_size)
{
    const float* vals = (const float*)d_in[0];
    const int*   gidx = (const int*)d_in[1];
    const int*   segs = (const int*)d_in[2];
    float*       out  = (float*)d_out;

    const int E     = in_sizes[1];
    const int n_seg = out_size / D;

    // 1) build CSR offsets
    {
        const int threads = 256;
        const int blocks = (E + threads - 1) / threads;
        build_csr_kernel<<<blocks, threads>>>(segs, E, n_seg);
    }
    // 2) warp-per-segment gather + mean
    {
        const int threads = 256;            // 8 warps/block
        const int wpb = threads / 32;
        const int blocks = (n_seg + wpb - 1) / wpb;
        agg_seg_mean_kernel<<<blocks, threads>>>(vals, gidx, out, n_seg);
    }
}

// round 4
// speedup vs baseline: 1.0167x; 1.0167x over previous
#include <cuda_runtime.h>
#include <cuda_bf16.h>
#include <cstdint>

// AggregationLayer: y[s] = mean over edges e with segment_ids[e]==s of
//                   layer_values[gather_idx[e], :]
// d_in[0]: layer_values f32 [N_SRC*64]
// d_in[1]: gather_idx   i32 [E]
// d_in[2]: segment_ids  i32 [E] (sorted ascending)
// out: f32 [n_seg*64]

#define D 64

// CSR row offsets scratch (n_seg <= 1M supported). +1 for the terminator.
__device__ int g_begin[1048577];

__global__ void __launch_bounds__(256)
build_csr_kernel(const int* __restrict__ segs, int E, int n_seg)
{
    int e = blockIdx.x * blockDim.x + threadIdx.x;
    if (e >= E) return;
    int s  = __ldg(segs + e);
    int sp = (e == 0) ? -1 : __ldg(segs + e - 1);
    // this thread owns boundaries (sp, s]
    for (int t = sp + 1; t <= s; ++t) g_begin[t] = e;
    if (e == E - 1) {
        for (int t = s + 1; t <= n_seg; ++t) g_begin[t] = E;
    }
}

__global__ void __launch_bounds__(256)
agg_seg_mean_kernel(const float* __restrict__ vals,
                    const int*   __restrict__ gidx,
                    float*       __restrict__ out,
                    int n_seg)
{
    const int warp_id = (blockIdx.x * blockDim.x + threadIdx.x) >> 5;
    const int lane    = threadIdx.x & 31;
    if (warp_id >= n_seg) return;
    const int s = warp_id;

    const int begin = __ldg(&g_begin[s]);
    const int end   = __ldg(&g_begin[s + 1]);

    const float2* __restrict__ vals2 = reinterpret_cast<const float2*>(vals);

    float ax = 0.f, ay = 0.f;

    for (int base = begin; base < end; base += 32) {
        const int n = min(32, end - base);
        // one coalesced load grabs up to 32 edge indices for the whole warp
        int myidx = 0;
        if (lane < n) myidx = __ldg(gidx + base + lane);

        int j = 0;
        for (; j + 4 <= n; j += 4) {
            int r0 = __shfl_sync(0xffffffffu, myidx, j + 0);
            int r1 = __shfl_sync(0xffffffffu, myidx, j + 1);
            int r2 = __shfl_sync(0xffffffffu, myidx, j + 2);
            int r3 = __shfl_sync(0xffffffffu, myidx, j + 3);
            float2 v0 = __ldg(vals2 + (size_t)r0 * (D/2) + lane);
            float2 v1 = __ldg(vals2 + (size_t)r1 * (D/2) + lane);
            float2 v2 = __ldg(vals2 + (size_t)r2 * (D/2) + lane);
            float2 v3 = __ldg(vals2 + (size_t)r3 * (D/2) + lane);
            ax += v0.x + v1.x + v2.x + v3.x;
            ay += v0.y + v1.y + v2.y + v3.y;
        }
        for (; j < n; ++j) {
            int r = __shfl_sync(0xffffffffu, myidx, j);
            float2 v = __ldg(vals2 + (size_t)r * (D/2) + lane);
            ax += v.x;
            ay += v.y;
        }
    }

    const int cnt = end - begin;
    const float inv = 1.0f / (float)max(cnt, 1);
    float2 res;
    res.x = ax * inv;
    res.y = ay * inv;
    reinterpret_cast<float2*>(out)[(size_t)s * (D/2) + lane] = res;
}

extern "C" void kernel_launch(void* const* d_in, const int* in_sizes, int n_in,
                              void* d_out, int out_size)
{
    const float* vals = (const float*)d_in[0];
    const int*   gidx = (const int*)d_in[1];
    const int*   segs = (const int*)d_in[2];
    float*       out  = (float*)d_out;

    const int E     = in_sizes[1];
    const int n_seg = out_size / D;

    // 1) build CSR offsets
    {
        const int threads = 256;
        const int blocks = (E + threads - 1) / threads;
        build_csr_kernel<<<blocks, threads>>>(segs, E, n_seg);
    }
    // 2) warp-per-segment gather + mean
    {
        const int threads = 256;            // 8 warps/block
        const int wpb = threads / 32;
        const int blocks = (n_seg + wpb - 1) / wpb;
        agg_seg_mean_kernel<<<blocks, threads>>>(vals, gidx, out, n_seg);
    }
}

// round 5
// speedup vs baseline: 1.0225x; 1.0057x over previous
#include <cuda_runtime.h>
#include <cuda_bf16.h>
#include <cstdint>

// AggregationLayer: y[s] = mean over edges e with segment_ids[e]==s of
//                   layer_values[gather_idx[e], :]
// d_in[0]: layer_values f32 [N_SRC*64]
// d_in[1]: gather_idx   i32 [E]
// d_in[2]: segment_ids  i32 [E] (sorted ascending)
// out: f32 [n_seg*64]

#define D 64

// CSR row offsets scratch (n_seg <= 1M supported). +1 for the terminator.
__device__ int g_begin[1048577];

__global__ void __launch_bounds__(256)
build_csr_kernel(const int* __restrict__ segs, int E, int n_seg)
{
    int e = blockIdx.x * blockDim.x + threadIdx.x;
    if (e >= E) return;
    int s  = __ldg(segs + e);
    int sp = (e == 0) ? -1 : __ldg(segs + e - 1);
    // this thread owns boundaries (sp, s]
    for (int t = sp + 1; t <= s; ++t) g_begin[t] = e;
    if (e == E - 1) {
        for (int t = s + 1; t <= n_seg; ++t) g_begin[t] = E;
    }
}

__global__ void __launch_bounds__(256)
agg_seg_mean_kernel(const float* __restrict__ vals,
                    const int*   __restrict__ gidx,
                    float*       __restrict__ out,
                    int n_seg)
{
    const int warp_id = (blockIdx.x * blockDim.x + threadIdx.x) >> 5;
    const int lane    = threadIdx.x & 31;
    if (warp_id >= n_seg) return;
    const int s = warp_id;

    const int begin = __ldg(&g_begin[s]);
    const int end   = __ldg(&g_begin[s + 1]);

    const float2* __restrict__ vals2 = reinterpret_cast<const float2*>(vals);

    float ax = 0.f, ay = 0.f;

    for (int base = begin; base < end; base += 32) {
        const int n = min(32, end - base);
        // one coalesced load grabs up to 32 edge indices for the whole warp
        int myidx = 0;
        if (lane < n) myidx = __ldg(gidx + base + lane);

        int j = 0;
        for (; j + 4 <= n; j += 4) {
            int r0 = __shfl_sync(0xffffffffu, myidx, j + 0);
            int r1 = __shfl_sync(0xffffffffu, myidx, j + 1);
            int r2 = __shfl_sync(0xffffffffu, myidx, j + 2);
            int r3 = __shfl_sync(0xffffffffu, myidx, j + 3);
            float2 v0 = __ldg(vals2 + (size_t)r0 * (D/2) + lane);
            float2 v1 = __ldg(vals2 + (size_t)r1 * (D/2) + lane);
            float2 v2 = __ldg(vals2 + (size_t)r2 * (D/2) + lane);
            float2 v3 = __ldg(vals2 + (size_t)r3 * (D/2) + lane);
            ax += v0.x + v1.x + v2.x + v3.x;
            ay += v0.y + v1.y + v2.y + v3.y;
        }
        for (; j < n; ++j) {
            int r = __shfl_sync(0xffffffffu, myidx, j);
            float2 v = __ldg(vals2 + (size_t)r * (D/2) + lane);
            ax += v.x;
            ay += v.y;
        }
    }

    const int cnt = end - begin;
    const float inv = 1.0f / (float)max(cnt, 1);
    float2 res;
    res.x = ax * inv;
    res.y = ay * inv;
    reinterpret_cast<float2*>(out)[(size_t)s * (D/2) + lane] = res;
}

extern "C" void kernel_launch(void* const* d_in, const int* in_sizes, int n_in,
                              void* d_out, int out_size)
{
    const float* vals = (const float*)d_in[0];
    const int*   gidx = (const int*)d_in[1];
    const int*   segs = (const int*)d_in[2];
    float*       out  = (float*)d_out;

    const int E     = in_sizes[1];
    const int n_seg = out_size / D;

    // 1) build CSR offsets
    {
        const int threads = 256;
        const int blocks = (E + threads - 1) / threads;
        build_csr_kernel<<<blocks, threads>>>(segs, E, n_seg);
    }
    // 2) warp-per-segment gather + mean
    {
        const int threads = 256;            // 8 warps/block
        const int wpb = threads / 32;
        const int blocks = (n_seg + wpb - 1) / wpb;
        agg_seg_mean_kernel<<<blocks, threads>>>(vals, gidx, out, n_seg);
    }
}